// round 1
// baseline (speedup 1.0000x reference)
#include <cuda_runtime.h>
#include <cstdint>
#include <cstddef>

// Problem dims
#define M1 4096
#define K1 1024
#define N1 4096
#define K2 4096   /* = N1 */
#define N2 1024

// ---------------- device scratch (static allocation only) ----------------
__device__ unsigned g_max[3];                 // max-abs bits: x, (w1,b1), (w2,b2)
__device__ float g_scales[6];                 // x_scale, s1, s2, mult1, mult2
__device__ signed char g_xq[M1 * K1];         // x quantized [M][K]
__device__ signed char g_w1qt[N1 * K1];       // w1 quantized, transposed [N][K]
__device__ signed char g_w2qt[N2 * K2];       // w2 quantized, transposed [N][K]
__device__ short g_b1q[N1];                   // int8-quantized bias, stored int16
__device__ short g_b2q[N2];
__device__ signed char g_hi[(size_t)M1 * N1]; // relu(o1) >> 8   (0..127)
__device__ unsigned char g_lo[(size_t)M1 * N1]; // relu(o1) & 255 (u8)

// ---------------- mma.sync wrappers ----------------
__device__ __forceinline__ void mma_s8s8(int* d, const unsigned* a, const unsigned* b) {
    asm volatile(
        "mma.sync.aligned.m16n8k32.row.col.s32.s8.s8.s32 "
        "{%0,%1,%2,%3}, {%4,%5,%6,%7}, {%8,%9}, {%0,%1,%2,%3};\n"
        : "+r"(d[0]), "+r"(d[1]), "+r"(d[2]), "+r"(d[3])
        : "r"(a[0]), "r"(a[1]), "r"(a[2]), "r"(a[3]), "r"(b[0]), "r"(b[1]));
}
__device__ __forceinline__ void mma_u8s8(int* d, const unsigned* a, const unsigned* b) {
    asm volatile(
        "mma.sync.aligned.m16n8k32.row.col.s32.u8.s8.s32 "
        "{%0,%1,%2,%3}, {%4,%5,%6,%7}, {%8,%9}, {%0,%1,%2,%3};\n"
        : "+r"(d[0]), "+r"(d[1]), "+r"(d[2]), "+r"(d[3])
        : "r"(a[0]), "r"(a[1]), "r"(a[2]), "r"(a[3]), "r"(b[0]), "r"(b[1]));
}

// ---------------- reductions + scales ----------------
__global__ void k_init() {
    if (threadIdx.x < 3) g_max[threadIdx.x] = 0u;
}

__global__ void k_maxabs(const float* __restrict__ a, int na4,
                         const float* __restrict__ b, int nb, int idx) {
    float m = 0.f;
    int tid = blockIdx.x * blockDim.x + threadIdx.x;
    int stride = gridDim.x * blockDim.x;
    const float4* a4 = (const float4*)a;
    for (int i = tid; i < na4; i += stride) {
        float4 v = a4[i];
        m = fmaxf(m, fmaxf(fmaxf(fabsf(v.x), fabsf(v.y)),
                           fmaxf(fabsf(v.z), fabsf(v.w))));
    }
    for (int i = tid; i < nb; i += stride) m = fmaxf(m, fabsf(b[i]));
#pragma unroll
    for (int o = 16; o; o >>= 1) m = fmaxf(m, __shfl_xor_sync(0xFFFFFFFFu, m, o));
    if ((threadIdx.x & 31) == 0) atomicMax(&g_max[idx], __float_as_uint(m));
}

__global__ void k_scales() {
    // replicate XLA f32 scalar math exactly
    float mx = __uint_as_float(g_max[0]);
    float m1 = __uint_as_float(g_max[1]);
    float m2 = __uint_as_float(g_max[2]);
    float x_scale = __fdiv_rn(mx, 127.0f);
    float s1 = __fdiv_rn(m1, 127.0f);
    float s2 = __fdiv_rn(m2, 127.0f);
    g_scales[0] = x_scale;
    g_scales[1] = s1;
    g_scales[2] = s2;
    // reference: scale_a * scale_b / target_scale (left-to-right f32)
    g_scales[3] = __fdiv_rn(__fmul_rn(x_scale, s1), s1);  // mult1
    g_scales[4] = __fdiv_rn(__fmul_rn(s1, s2), s2);       // mult2
}

// ---------------- quantization ----------------
__global__ void k_quant_x(const float* __restrict__ x, int n4) {
    int i = blockIdx.x * blockDim.x + threadIdx.x;
    if (i >= n4) return;
    float s = g_scales[0];
    float4 v = ((const float4*)x)[i];
    char4 q;
    q.x = (signed char)(int)rintf(__fdiv_rn(v.x, s));
    q.y = (signed char)(int)rintf(__fdiv_rn(v.y, s));
    q.z = (signed char)(int)rintf(__fdiv_rn(v.z, s));
    q.w = (signed char)(int)rintf(__fdiv_rn(v.w, s));
    ((char4*)g_xq)[i] = q;
}

// w: [K][N] f32 row-major  ->  out: [N][K] int8 (transposed)
__global__ void k_quant_wt(const float* __restrict__ w, int K, int N, int which) {
    __shared__ float t[32][33];
    signed char* out = which ? g_w2qt : g_w1qt;
    float s = g_scales[which ? 2 : 1];
    int k0 = blockIdx.y * 32, n0 = blockIdx.x * 32;
    int tx = threadIdx.x, ty = threadIdx.y;  // 32 x 8
#pragma unroll
    for (int j = 0; j < 32; j += 8)
        t[ty + j][tx] = w[(size_t)(k0 + ty + j) * N + (n0 + tx)];
    __syncthreads();
#pragma unroll
    for (int j = 0; j < 32; j += 8) {
        float v = t[tx][ty + j];
        out[(size_t)(n0 + ty + j) * K + (k0 + tx)] =
            (signed char)(int)rintf(__fdiv_rn(v, s));
    }
}

__global__ void k_quant_bias(const float* __restrict__ b1, const float* __restrict__ b2) {
    int i = blockIdx.x * blockDim.x + threadIdx.x;
    if (i < N1) g_b1q[i] = (short)(signed char)(int)rintf(__fdiv_rn(b1[i], g_scales[1]));
    if (i < N2) g_b2q[i] = (short)(signed char)(int)rintf(__fdiv_rn(b2[i], g_scales[2]));
}

// ---------------- GEMM1: xq[4096,1024] @ w1qt[4096,1024]^T -> hi/lo split ----------------
// block 128x128, 8 warps (2 m x 4 n), warp tile 64x32, K-step 32
__global__ void __launch_bounds__(256) k_gemm1() {
    __shared__ signed char As[128 * 48];
    __shared__ signed char Bs[128 * 48];
    const int bm = blockIdx.y * 128;
    const int bn = blockIdx.x * 128;
    const int tid = threadIdx.x;
    const int lane = tid & 31, warp = tid >> 5;
    const int wm = (warp >> 2) * 64;
    const int wn = (warp & 3) * 32;
    const int gid = lane >> 2, tg = lane & 3;

    int acc[4][4][4];
#pragma unroll
    for (int i = 0; i < 4; i++)
#pragma unroll
        for (int j = 0; j < 4; j++)
#pragma unroll
            for (int k = 0; k < 4; k++) acc[i][j][k] = 0;

    const int lr = tid >> 1;
    const int lc = (tid & 1) * 16;
    const signed char* Ag = g_xq + (size_t)(bm + lr) * K1 + lc;
    const signed char* Bg = g_w1qt + (size_t)(bn + lr) * K1 + lc;

    for (int kc = 0; kc < K1; kc += 32) {
        *(int4*)&As[lr * 48 + lc] = *(const int4*)(Ag + kc);
        *(int4*)&Bs[lr * 48 + lc] = *(const int4*)(Bg + kc);
        __syncthreads();
        unsigned a[4][4], b[4][2];
#pragma unroll
        for (int mt = 0; mt < 4; mt++) {
            int row = wm + mt * 16 + gid;
            a[mt][0] = *(const unsigned*)&As[row * 48 + tg * 4];
            a[mt][1] = *(const unsigned*)&As[(row + 8) * 48 + tg * 4];
            a[mt][2] = *(const unsigned*)&As[row * 48 + tg * 4 + 16];
            a[mt][3] = *(const unsigned*)&As[(row + 8) * 48 + tg * 4 + 16];
        }
#pragma unroll
        for (int nt = 0; nt < 4; nt++) {
            int nr = wn + nt * 8 + gid;
            b[nt][0] = *(const unsigned*)&Bs[nr * 48 + tg * 4];
            b[nt][1] = *(const unsigned*)&Bs[nr * 48 + tg * 4 + 16];
        }
#pragma unroll
        for (int mt = 0; mt < 4; mt++)
#pragma unroll
            for (int nt = 0; nt < 4; nt++)
                mma_s8s8(acc[mt][nt], a[mt], b[nt]);
        __syncthreads();
    }

    const float mult1 = g_scales[3];
#pragma unroll
    for (int mt = 0; mt < 4; mt++)
#pragma unroll
        for (int nt = 0; nt < 4; nt++)
#pragma unroll
            for (int i = 0; i < 4; i++) {
                int r = bm + wm + mt * 16 + gid + ((i >> 1) << 3);
                int c = bn + wn + nt * 8 + tg * 2 + (i & 1);
                int q = (int)rintf(__fmul_rn((float)acc[mt][nt][i], mult1));
                short o = (short)((short)q + g_b1q[c]);
                if (o < 0) o = 0;
                size_t idx = (size_t)r * N1 + c;
                g_hi[idx] = (signed char)(o >> 8);
                g_lo[idx] = (unsigned char)(o & 0xFF);
            }
}

// ---------------- GEMM2: (256*hi + lo)[4096,4096] @ w2qt[1024,4096]^T -> out f32 ----------------
// block 128x64, 8 warps (2 m x 4 n), warp tile 64x16, K-step 32, dual accum chains
__global__ void __launch_bounds__(256) k_gemm2(float* __restrict__ out) {
    __shared__ signed char Hs[128 * 48];
    __shared__ unsigned char Ls[128 * 48];
    __shared__ signed char Bs[64 * 48];
    const int bm = blockIdx.y * 128;
    const int bn = blockIdx.x * 64;
    const int tid = threadIdx.x;
    const int lane = tid & 31, warp = tid >> 5;
    const int wm = (warp >> 2) * 64;
    const int wn = (warp & 3) * 16;
    const int gid = lane >> 2, tg = lane & 3;

    int acch[4][2][4], accl[4][2][4];
#pragma unroll
    for (int i = 0; i < 4; i++)
#pragma unroll
        for (int j = 0; j < 2; j++)
#pragma unroll
            for (int k = 0; k < 4; k++) { acch[i][j][k] = 0; accl[i][j][k] = 0; }

    const int lr = tid >> 1;
    const int lc = (tid & 1) * 16;
    const size_t abase = (size_t)(bm + lr) * K2 + lc;
    const size_t bbase = (size_t)(bn + lr) * K2 + lc;  // valid only for tid<128

    for (int kc = 0; kc < K2; kc += 32) {
        *(int4*)&Hs[lr * 48 + lc] = *(const int4*)(g_hi + abase + kc);
        *(int4*)&Ls[lr * 48 + lc] = *(const int4*)(g_lo + abase + kc);
        if (tid < 128)
            *(int4*)&Bs[lr * 48 + lc] = *(const int4*)(g_w2qt + bbase + kc);
        __syncthreads();
        unsigned ah[4][4], al[4][4], b[2][2];
#pragma unroll
        for (int mt = 0; mt < 4; mt++) {
            int row = wm + mt * 16 + gid;
            ah[mt][0] = *(const unsigned*)&Hs[row * 48 + tg * 4];
            ah[mt][1] = *(const unsigned*)&Hs[(row + 8) * 48 + tg * 4];
            ah[mt][2] = *(const unsigned*)&Hs[row * 48 + tg * 4 + 16];
            ah[mt][3] = *(const unsigned*)&Hs[(row + 8) * 48 + tg * 4 + 16];
            al[mt][0] = *(const unsigned*)&Ls[row * 48 + tg * 4];
            al[mt][1] = *(const unsigned*)&Ls[(row + 8) * 48 + tg * 4];
            al[mt][2] = *(const unsigned*)&Ls[row * 48 + tg * 4 + 16];
            al[mt][3] = *(const unsigned*)&Ls[(row + 8) * 48 + tg * 4 + 16];
        }
#pragma unroll
        for (int nt = 0; nt < 2; nt++) {
            int nr = wn + nt * 8 + gid;
            b[nt][0] = *(const unsigned*)&Bs[nr * 48 + tg * 4];
            b[nt][1] = *(const unsigned*)&Bs[nr * 48 + tg * 4 + 16];
        }
#pragma unroll
        for (int mt = 0; mt < 4; mt++)
#pragma unroll
            for (int nt = 0; nt < 2; nt++) {
                mma_s8s8(acch[mt][nt], ah[mt], b[nt]);
                mma_u8s8(accl[mt][nt], al[mt], b[nt]);
            }
        __syncthreads();
    }

    const float mult2 = g_scales[4];
    const float s2 = g_scales[2];
#pragma unroll
    for (int mt = 0; mt < 4; mt++)
#pragma unroll
        for (int nt = 0; nt < 2; nt++)
#pragma unroll
            for (int i = 0; i < 4; i++) {
                int r = bm + wm + mt * 16 + gid + ((i >> 1) << 3);
                int c = bn + wn + nt * 8 + tg * 2 + (i & 1);
                // int32 wraparound combine == reference int32 accumulation mod 2^32
                int acc = accl[mt][nt][i] + acch[mt][nt][i] * 256;
                int q = (int)rintf(__fmul_rn((float)acc, mult2));
                short o = (short)((short)q + g_b2q[c]);
                out[(size_t)r * N2 + c] = __fmul_rn((float)o, s2);
            }
}

// ---------------- launcher ----------------
extern "C" void kernel_launch(void* const* d_in, const int* in_sizes, int n_in,
                              void* d_out, int out_size) {
    const float* x = (const float*)d_in[0];    // [4096, 1024]
    const float* w1f = (const float*)d_in[1];  // [1024, 4096]
    const float* b1f = (const float*)d_in[2];  // [4096]
    const float* w2f = (const float*)d_in[3];  // [4096, 1024]
    const float* b2f = (const float*)d_in[4];  // [1024]
    float* out = (float*)d_out;                // [4096, 1024]

    k_init<<<1, 32>>>();
    k_maxabs<<<512, 256>>>(x, (M1 * K1) / 4, nullptr, 0, 0);
    k_maxabs<<<512, 256>>>(w1f, (K1 * N1) / 4, b1f, N1, 1);
    k_maxabs<<<512, 256>>>(w2f, (K2 * N2) / 4, b2f, N2, 2);
    k_scales<<<1, 1>>>();
    k_quant_x<<<(M1 * K1 / 4 + 255) / 256, 256>>>(x, M1 * K1 / 4);
    k_quant_wt<<<dim3(N1 / 32, K1 / 32), dim3(32, 8)>>>(w1f, K1, N1, 0);
    k_quant_wt<<<dim3(N2 / 32, K2 / 32), dim3(32, 8)>>>(w2f, K2, N2, 1);
    k_quant_bias<<<16, 256>>>(b1f, b2f);
    k_gemm1<<<dim3(N1 / 128, M1 / 128), 256>>>();
    k_gemm2<<<dim3(N2 / 64, M1 / 128), 256>>>(out);
}

// round 2
// speedup vs baseline: 1.0519x; 1.0519x over previous
#include <cuda_runtime.h>
#include <cstdint>
#include <cstddef>

// Problem dims
#define M1 4096
#define K1 1024
#define N1 4096
#define K2 4096   /* = N1 */
#define N2 1024

#define STAGES 3

// ---------------- device scratch (static allocation only) ----------------
__device__ unsigned g_max[3];
__device__ float g_scales[6];
__device__ signed char g_xq[M1 * K1];
__device__ signed char g_w1qt[N1 * K1];
__device__ signed char g_w2qt[N2 * K2];
__device__ short g_b1q[N1];
__device__ short g_b2q[N2];
__device__ signed char g_hi[(size_t)M1 * N1];
__device__ unsigned char g_lo[(size_t)M1 * N1];

// ---------------- asm helpers ----------------
__device__ __forceinline__ void mma_s8s8(int* d, const unsigned* a, const unsigned* b) {
    asm volatile(
        "mma.sync.aligned.m16n8k32.row.col.s32.s8.s8.s32 "
        "{%0,%1,%2,%3}, {%4,%5,%6,%7}, {%8,%9}, {%0,%1,%2,%3};\n"
        : "+r"(d[0]), "+r"(d[1]), "+r"(d[2]), "+r"(d[3])
        : "r"(a[0]), "r"(a[1]), "r"(a[2]), "r"(a[3]), "r"(b[0]), "r"(b[1]));
}
__device__ __forceinline__ void mma_u8s8(int* d, const unsigned* a, const unsigned* b) {
    asm volatile(
        "mma.sync.aligned.m16n8k32.row.col.s32.u8.s8.s32 "
        "{%0,%1,%2,%3}, {%4,%5,%6,%7}, {%8,%9}, {%0,%1,%2,%3};\n"
        : "+r"(d[0]), "+r"(d[1]), "+r"(d[2]), "+r"(d[3])
        : "r"(a[0]), "r"(a[1]), "r"(a[2]), "r"(a[3]), "r"(b[0]), "r"(b[1]));
}
__device__ __forceinline__ void cp16(unsigned dst, const void* src) {
    asm volatile("cp.async.cg.shared.global [%0], [%1], 16;\n" :: "r"(dst), "l"(src));
}
__device__ __forceinline__ void cp_commit() {
    asm volatile("cp.async.commit_group;\n");
}
template <int N>
__device__ __forceinline__ void cp_wait() {
    asm volatile("cp.async.wait_group %0;\n" :: "n"(N));
}

// ---------------- reductions + scales ----------------
__global__ void k_init() {
    if (threadIdx.x < 3) g_max[threadIdx.x] = 0u;
}

__global__ void k_maxabs(const float* __restrict__ a, int na4,
                         const float* __restrict__ b, int nb, int idx) {
    float m = 0.f;
    int tid = blockIdx.x * blockDim.x + threadIdx.x;
    int stride = gridDim.x * blockDim.x;
    const float4* a4 = (const float4*)a;
    for (int i = tid; i < na4; i += stride) {
        float4 v = a4[i];
        m = fmaxf(m, fmaxf(fmaxf(fabsf(v.x), fabsf(v.y)),
                           fmaxf(fabsf(v.z), fabsf(v.w))));
    }
    for (int i = tid; i < nb; i += stride) m = fmaxf(m, fabsf(b[i]));
#pragma unroll
    for (int o = 16; o; o >>= 1) m = fmaxf(m, __shfl_xor_sync(0xFFFFFFFFu, m, o));
    if ((threadIdx.x & 31) == 0) atomicMax(&g_max[idx], __float_as_uint(m));
}

__global__ void k_scales() {
    float mx = __uint_as_float(g_max[0]);
    float m1 = __uint_as_float(g_max[1]);
    float m2 = __uint_as_float(g_max[2]);
    float x_scale = __fdiv_rn(mx, 127.0f);
    float s1 = __fdiv_rn(m1, 127.0f);
    float s2 = __fdiv_rn(m2, 127.0f);
    g_scales[0] = x_scale;
    g_scales[1] = s1;
    g_scales[2] = s2;
    g_scales[3] = __fdiv_rn(__fmul_rn(x_scale, s1), s1);  // mult1
    g_scales[4] = __fdiv_rn(__fmul_rn(s1, s2), s2);       // mult2
}

// ---------------- quantization ----------------
__global__ void k_quant_x(const float* __restrict__ x, int n4) {
    int i = blockIdx.x * blockDim.x + threadIdx.x;
    if (i >= n4) return;
    float s = g_scales[0];
    float4 v = ((const float4*)x)[i];
    char4 q;
    q.x = (signed char)(int)rintf(__fdiv_rn(v.x, s));
    q.y = (signed char)(int)rintf(__fdiv_rn(v.y, s));
    q.z = (signed char)(int)rintf(__fdiv_rn(v.z, s));
    q.w = (signed char)(int)rintf(__fdiv_rn(v.w, s));
    ((char4*)g_xq)[i] = q;
}

// w: [K][N] f32 row-major  ->  out: [N][K] int8 (transposed)
__global__ void k_quant_wt(const float* __restrict__ w, int K, int N, int which) {
    __shared__ float t[32][33];
    signed char* out = which ? g_w2qt : g_w1qt;
    float s = g_scales[which ? 2 : 1];
    int k0 = blockIdx.y * 32, n0 = blockIdx.x * 32;
    int tx = threadIdx.x, ty = threadIdx.y;  // 32 x 8
#pragma unroll
    for (int j = 0; j < 32; j += 8)
        t[ty + j][tx] = w[(size_t)(k0 + ty + j) * N + (n0 + tx)];
    __syncthreads();
#pragma unroll
    for (int j = 0; j < 32; j += 8) {
        float v = t[tx][ty + j];
        out[(size_t)(n0 + ty + j) * K + (k0 + tx)] =
            (signed char)(int)rintf(__fdiv_rn(v, s));
    }
}

__global__ void k_quant_bias(const float* __restrict__ b1, const float* __restrict__ b2) {
    int i = blockIdx.x * blockDim.x + threadIdx.x;
    if (i < N1) g_b1q[i] = (short)(signed char)(int)rintf(__fdiv_rn(b1[i], g_scales[1]));
    if (i < N2) g_b2q[i] = (short)(signed char)(int)rintf(__fdiv_rn(b2[i], g_scales[2]));
}

// ---------------- GEMM1: xq[4096,1024] @ w1qt[4096,1024]^T -> hi/lo split ----------------
// block 128x128, 8 warps (2m x 4n), warp 64x32, BK=64, 3-stage cp.async pipeline
#define G1_ROWB 80            // padded row bytes for BK=64
#define G1_TILE (128 * G1_ROWB)
__global__ void __launch_bounds__(256) k_gemm1() {
    extern __shared__ signed char sm1[];
    signed char* As = sm1;
    signed char* Bs = sm1 + STAGES * G1_TILE;

    const int bm = blockIdx.y * 128;
    const int bn = blockIdx.x * 128;
    const int tid = threadIdx.x;
    const int lane = tid & 31, warp = tid >> 5;
    const int wm = (warp >> 2) * 64;
    const int wn = (warp & 3) * 32;
    const int gid = lane >> 2, tg = lane & 3;

    int acc[4][4][4];
#pragma unroll
    for (int i = 0; i < 4; i++)
#pragma unroll
        for (int j = 0; j < 4; j++)
#pragma unroll
            for (int k = 0; k < 4; k++) acc[i][j][k] = 0;

    // cp.async mapping: each thread loads 2x16B per tile
    const int lr = tid >> 1;
    const int lcb = (tid & 1) * 32;
    const signed char* Ag = g_xq + (size_t)(bm + lr) * K1 + lcb;
    const signed char* Bg = g_w1qt + (size_t)(bn + lr) * K1 + lcb;
    const unsigned sA = (unsigned)__cvta_generic_to_shared(As) + lr * G1_ROWB + lcb;
    const unsigned sB = (unsigned)__cvta_generic_to_shared(Bs) + lr * G1_ROWB + lcb;

    const int NK = K1 / 64;  // 16

#pragma unroll
    for (int s = 0; s < STAGES - 1; s++) {
        cp16(sA + s * G1_TILE, Ag + s * 64);
        cp16(sA + s * G1_TILE + 16, Ag + s * 64 + 16);
        cp16(sB + s * G1_TILE, Bg + s * 64);
        cp16(sB + s * G1_TILE + 16, Bg + s * 64 + 16);
        cp_commit();
    }

    for (int i = 0; i < NK; i++) {
        cp_wait<STAGES - 2>();
        __syncthreads();
        {
            int pf = i + STAGES - 1;
            if (pf < NK) {
                int ps = pf % STAGES;
                cp16(sA + ps * G1_TILE, Ag + pf * 64);
                cp16(sA + ps * G1_TILE + 16, Ag + pf * 64 + 16);
                cp16(sB + ps * G1_TILE, Bg + pf * 64);
                cp16(sB + ps * G1_TILE + 16, Bg + pf * 64 + 16);
            }
            cp_commit();
        }
        const signed char* A = As + (i % STAGES) * G1_TILE;
        const signed char* B = Bs + (i % STAGES) * G1_TILE;
#pragma unroll
        for (int kk = 0; kk < 2; kk++) {
            const int ko = kk * 32;
            unsigned a[4][4], b[4][2];
#pragma unroll
            for (int mt = 0; mt < 4; mt++) {
                int row = wm + mt * 16 + gid;
                a[mt][0] = *(const unsigned*)&A[row * G1_ROWB + tg * 4 + ko];
                a[mt][1] = *(const unsigned*)&A[(row + 8) * G1_ROWB + tg * 4 + ko];
                a[mt][2] = *(const unsigned*)&A[row * G1_ROWB + tg * 4 + 16 + ko];
                a[mt][3] = *(const unsigned*)&A[(row + 8) * G1_ROWB + tg * 4 + 16 + ko];
            }
#pragma unroll
            for (int nt = 0; nt < 4; nt++) {
                int nr = wn + nt * 8 + gid;
                b[nt][0] = *(const unsigned*)&B[nr * G1_ROWB + tg * 4 + ko];
                b[nt][1] = *(const unsigned*)&B[nr * G1_ROWB + tg * 4 + 16 + ko];
            }
#pragma unroll
            for (int mt = 0; mt < 4; mt++)
#pragma unroll
                for (int nt = 0; nt < 4; nt++)
                    mma_s8s8(acc[mt][nt], a[mt], b[nt]);
        }
    }

    const float mult1 = g_scales[3];
#pragma unroll
    for (int mt = 0; mt < 4; mt++)
#pragma unroll
        for (int nt = 0; nt < 4; nt++) {
            int c = bn + wn + nt * 8 + tg * 2;
            short bias0 = g_b1q[c], bias1 = g_b1q[c + 1];
#pragma unroll
            for (int half = 0; half < 2; half++) {
                int r = bm + wm + mt * 16 + gid + half * 8;
                int q0 = (int)rintf(__fmul_rn((float)acc[mt][nt][half * 2 + 0], mult1));
                int q1 = (int)rintf(__fmul_rn((float)acc[mt][nt][half * 2 + 1], mult1));
                short o0 = (short)((short)q0 + bias0);
                short o1 = (short)((short)q1 + bias1);
                if (o0 < 0) o0 = 0;
                if (o1 < 0) o1 = 0;
                size_t idx = (size_t)r * N1 + c;
                unsigned short hp = (unsigned short)(((unsigned char)(o0 >> 8)) |
                                                    ((unsigned)((unsigned char)(o1 >> 8)) << 8));
                unsigned short lp = (unsigned short)(((unsigned char)(o0 & 0xFF)) |
                                                    ((unsigned)((unsigned char)(o1 & 0xFF)) << 8));
                *(unsigned short*)&g_hi[idx] = hp;
                *(unsigned short*)&g_lo[idx] = lp;
            }
        }
}

// ---------------- GEMM2: (256*hi + lo)[4096,4096] @ w2qt[1024,4096]^T -> out f32 ----------------
// block 128x64, 8 warps (2m x 4n), warp 64x16, BK=64, 3-stage cp.async, dual accum chains
#define G2_ROWB 80
#define G2_ATILE (128 * G2_ROWB)
#define G2_BTILE (64 * G2_ROWB)
#define G2_STAGE (2 * G2_ATILE + G2_BTILE)
__global__ void __launch_bounds__(256) k_gemm2(float* __restrict__ out) {
    extern __shared__ signed char sm2[];
    // per-stage layout: [Hs | Ls | Bs]
    const int bm = blockIdx.y * 128;
    const int bn = blockIdx.x * 64;
    const int tid = threadIdx.x;
    const int lane = tid & 31, warp = tid >> 5;
    const int wm = (warp >> 2) * 64;
    const int wn = (warp & 3) * 16;
    const int gid = lane >> 2, tg = lane & 3;

    int acch[4][2][4], accl[4][2][4];
#pragma unroll
    for (int i = 0; i < 4; i++)
#pragma unroll
        for (int j = 0; j < 2; j++)
#pragma unroll
            for (int k = 0; k < 4; k++) { acch[i][j][k] = 0; accl[i][j][k] = 0; }

    const int lr = tid >> 1;
    const int lcb = (tid & 1) * 32;
    const signed char* Hg = g_hi + (size_t)(bm + lr) * K2 + lcb;
    const signed char* Lg = (const signed char*)g_lo + (size_t)(bm + lr) * K2 + lcb;
    const int brow = tid >> 2;
    const int bcol = (tid & 3) * 16;
    const signed char* Bg = g_w2qt + (size_t)(bn + brow) * K2 + bcol;

    const unsigned smem0 = (unsigned)__cvta_generic_to_shared(sm2);
    const unsigned sH = smem0 + lr * G2_ROWB + lcb;
    const unsigned sL = smem0 + G2_ATILE + lr * G2_ROWB + lcb;
    const unsigned sBw = smem0 + 2 * G2_ATILE + brow * G2_ROWB + bcol;

    const int NK = K2 / 64;  // 64

#pragma unroll
    for (int s = 0; s < STAGES - 1; s++) {
        cp16(sH + s * G2_STAGE, Hg + s * 64);
        cp16(sH + s * G2_STAGE + 16, Hg + s * 64 + 16);
        cp16(sL + s * G2_STAGE, Lg + s * 64);
        cp16(sL + s * G2_STAGE + 16, Lg + s * 64 + 16);
        cp16(sBw + s * G2_STAGE, Bg + s * 64);
        cp_commit();
    }

    for (int i = 0; i < NK; i++) {
        cp_wait<STAGES - 2>();
        __syncthreads();
        {
            int pf = i + STAGES - 1;
            if (pf < NK) {
                int ps = pf % STAGES;
                cp16(sH + ps * G2_STAGE, Hg + pf * 64);
                cp16(sH + ps * G2_STAGE + 16, Hg + pf * 64 + 16);
                cp16(sL + ps * G2_STAGE, Lg + pf * 64);
                cp16(sL + ps * G2_STAGE + 16, Lg + pf * 64 + 16);
                cp16(sBw + ps * G2_STAGE, Bg + pf * 64);
            }
            cp_commit();
        }
        const signed char* H = sm2 + (i % STAGES) * G2_STAGE;
        const signed char* L = H + G2_ATILE;
        const signed char* B = H + 2 * G2_ATILE;
#pragma unroll
        for (int kk = 0; kk < 2; kk++) {
            const int ko = kk * 32;
            unsigned ah[4][4], al[4][4], b[2][2];
#pragma unroll
            for (int mt = 0; mt < 4; mt++) {
                int row = wm + mt * 16 + gid;
                ah[mt][0] = *(const unsigned*)&H[row * G2_ROWB + tg * 4 + ko];
                ah[mt][1] = *(const unsigned*)&H[(row + 8) * G2_ROWB + tg * 4 + ko];
                ah[mt][2] = *(const unsigned*)&H[row * G2_ROWB + tg * 4 + 16 + ko];
                ah[mt][3] = *(const unsigned*)&H[(row + 8) * G2_ROWB + tg * 4 + 16 + ko];
                al[mt][0] = *(const unsigned*)&L[row * G2_ROWB + tg * 4 + ko];
                al[mt][1] = *(const unsigned*)&L[(row + 8) * G2_ROWB + tg * 4 + ko];
                al[mt][2] = *(const unsigned*)&L[row * G2_ROWB + tg * 4 + 16 + ko];
                al[mt][3] = *(const unsigned*)&L[(row + 8) * G2_ROWB + tg * 4 + 16 + ko];
            }
#pragma unroll
            for (int nt = 0; nt < 2; nt++) {
                int nr = wn + nt * 8 + gid;
                b[nt][0] = *(const unsigned*)&B[nr * G2_ROWB + tg * 4 + ko];
                b[nt][1] = *(const unsigned*)&B[nr * G2_ROWB + tg * 4 + 16 + ko];
            }
#pragma unroll
            for (int mt = 0; mt < 4; mt++)
#pragma unroll
                for (int nt = 0; nt < 2; nt++) {
                    mma_s8s8(acch[mt][nt], ah[mt], b[nt]);
                    mma_u8s8(accl[mt][nt], al[mt], b[nt]);
                }
        }
    }

    const float mult2 = g_scales[4];
    const float s2 = g_scales[2];
#pragma unroll
    for (int mt = 0; mt < 4; mt++)
#pragma unroll
        for (int nt = 0; nt < 2; nt++) {
            int c = bn + wn + nt * 8 + tg * 2;
            short bias0 = g_b2q[c], bias1 = g_b2q[c + 1];
#pragma unroll
            for (int half = 0; half < 2; half++) {
                int r = bm + wm + mt * 16 + gid + half * 8;
                int v0 = accl[mt][nt][half * 2 + 0] + acch[mt][nt][half * 2 + 0] * 256;
                int v1 = accl[mt][nt][half * 2 + 1] + acch[mt][nt][half * 2 + 1] * 256;
                int q0 = (int)rintf(__fmul_rn((float)v0, mult2));
                int q1 = (int)rintf(__fmul_rn((float)v1, mult2));
                short o0 = (short)((short)q0 + bias0);
                short o1 = (short)((short)q1 + bias1);
                float2 ov = make_float2(__fmul_rn((float)o0, s2), __fmul_rn((float)o1, s2));
                *(float2*)&out[(size_t)r * N2 + c] = ov;
            }
        }
}

// ---------------- launcher ----------------
extern "C" void kernel_launch(void* const* d_in, const int* in_sizes, int n_in,
                              void* d_out, int out_size) {
    const float* x = (const float*)d_in[0];    // [4096, 1024]
    const float* w1f = (const float*)d_in[1];  // [1024, 4096]
    const float* b1f = (const float*)d_in[2];  // [4096]
    const float* w2f = (const float*)d_in[3];  // [4096, 1024]
    const float* b2f = (const float*)d_in[4];  // [1024]
    float* out = (float*)d_out;                // [4096, 1024]

    static bool attr_done = false;
    if (!attr_done) {
        cudaFuncSetAttribute(k_gemm1, cudaFuncAttributeMaxDynamicSharedMemorySize,
                             STAGES * 2 * G1_TILE);
        cudaFuncSetAttribute(k_gemm2, cudaFuncAttributeMaxDynamicSharedMemorySize,
                             STAGES * G2_STAGE);
        attr_done = true;
    }

    k_init<<<1, 32>>>();
    k_maxabs<<<512, 256>>>(x, (M1 * K1) / 4, nullptr, 0, 0);
    k_maxabs<<<512, 256>>>(w1f, (K1 * N1) / 4, b1f, N1, 1);
    k_maxabs<<<512, 256>>>(w2f, (K2 * N2) / 4, b2f, N2, 2);
    k_scales<<<1, 1>>>();
    k_quant_x<<<(M1 * K1 / 4 + 255) / 256, 256>>>(x, M1 * K1 / 4);
    k_quant_wt<<<dim3(N1 / 32, K1 / 32), dim3(32, 8)>>>(w1f, K1, N1, 0);
    k_quant_wt<<<dim3(N2 / 32, K2 / 32), dim3(32, 8)>>>(w2f, K2, N2, 1);
    k_quant_bias<<<16, 256>>>(b1f, b2f);
    k_gemm1<<<dim3(N1 / 128, M1 / 128), 256, STAGES * 2 * G1_TILE>>>();
    k_gemm2<<<dim3(N2 / 64, M1 / 128), 256, STAGES * G2_STAGE>>>(out);
}

// round 6
// speedup vs baseline: 2.6523x; 2.5214x over previous
#include <cuda_runtime.h>
#include <cuda_bf16.h>
#include <cstdint>
#include <cstddef>

// Problem dims
#define M1 4096
#define K1 1024
#define N1 4096
#define K2 4096   /* = N1 */
#define N2 1024

// ---- arch-specific feature detection (tcgen05 availability in this pass) ----
#if defined(__CUDA_ARCH__) && (__CUDA_ARCH__ >= 1000) &&                      \
    (defined(__CUDA_ARCH_FEAT_SM103_ALL) || defined(__CUDA_ARCH_FEAT_SM100_ALL) || \
     defined(__CUDA_ARCH_SPECIFIC__) || defined(__CUDA_ARCH_FAMILY_SPECIFIC__))
#define HAS_TC 1
#else
#define HAS_TC 0
#endif

// ---------------- device scratch ----------------
__device__ unsigned g_max[3];
__device__ float g_scales[6];
__device__ __nv_bfloat16 g_x16[M1 * K1];           // x quantized, bf16-exact ints
__device__ __nv_bfloat16 g_w1t[N1 * K1];           // w1 quantized, transposed [N][K]
__device__ __nv_bfloat16 g_w2t[N2 * K2];           // w2 quantized, transposed [N][K]
__device__ short g_b1q[N1];
__device__ short g_b2q[N2];
// relu(o1) split into 3x 5-bit digits, stored bf16 (exact)
__device__ __nv_bfloat16 g_p0[(size_t)M1 * N1];
__device__ __nv_bfloat16 g_p1[(size_t)M1 * N1];
__device__ __nv_bfloat16 g_p2[(size_t)M1 * N1];

// ---------------- common helpers ----------------
__device__ __forceinline__ uint32_t smem_u32(const void* p) {
    uint32_t a;
    asm("{ .reg .u64 t; cvta.to.shared.u64 t, %1; cvt.u32.u64 %0, t; }" : "=r"(a) : "l"(p));
    return a;
}
__device__ __forceinline__ void cp16(unsigned dst, const void* src) {
    asm volatile("cp.async.cg.shared.global [%0], [%1], 16;\n" :: "r"(dst), "l"(src));
}
__device__ __forceinline__ void cp_commit() { asm volatile("cp.async.commit_group;\n"); }
template <int N>
__device__ __forceinline__ void cp_wait() { asm volatile("cp.async.wait_group %0;\n" :: "n"(N)); }

#define SW128(o) ((o) ^ (((o) >> 3) & 0x70))

__device__ __forceinline__ unsigned pack_bf16(float lo, float hi) {
    unsigned r;
    asm("cvt.rn.bf16x2.f32 %0, %1, %2;" : "=r"(r) : "f"(hi), "f"(lo));
    return r;
}

#if HAS_TC
// ---------------- tcgen05 helpers (arch-specific pass only) ----------------
#define MBAR_INIT(a, c) \
    asm volatile("mbarrier.init.shared.b64 [%0], %1;" :: "r"(a), "r"(c) : "memory")
#define MBAR_WAIT(a, par) do {                                                  \
    unsigned _m = (a), _p = (par), _d;                                          \
    asm volatile("{\n\t.reg .pred p;\n\t"                                       \
        "mbarrier.try_wait.parity.acquire.cta.shared::cta.b64 p, [%1], %2;\n\t" \
        "selp.b32 %0, 1, 0, p;\n\t}"                                            \
        : "=r"(_d) : "r"(_m), "r"(_p) : "memory");                              \
    if (!_d) {                                                                  \
        asm volatile("{\n\t.reg .pred P1;\n\t"                                  \
            "W%=:\n\t"                                                          \
            "mbarrier.try_wait.parity.acquire.cta.shared::cta.b64 P1, [%0], %1, 0x989680;\n\t" \
            "@P1 bra.uni D%=;\n\tbra.uni W%=;\n\tD%=:\n\t}"                     \
            :: "r"(_m), "r"(_p) : "memory");                                    \
    }                                                                           \
} while (0)

#define TC_ALLOC(sl, n) \
    asm volatile("tcgen05.alloc.cta_group::1.sync.aligned.shared::cta.b32 [%0], %1;" \
                 :: "r"(sl), "r"(n) : "memory")
#define TC_DEALLOC(t, n) \
    asm volatile("tcgen05.dealloc.cta_group::1.sync.aligned.b32 %0, %1;" :: "r"(t), "r"(n))
#define TC_RELINQ() asm volatile("tcgen05.relinquish_alloc_permit.cta_group::1.sync.aligned;")
#define TC_COMMIT(m) \
    asm volatile("tcgen05.commit.cta_group::1.mbarrier::arrive::one.shared::cluster.b64 [%0];" \
                 :: "r"(m) : "memory")
#define TC_FENCE_AFTER() asm volatile("tcgen05.fence::after_thread_sync;" ::: "memory")
#define TC_FENCE_BEFORE() asm volatile("tcgen05.fence::before_thread_sync;" ::: "memory")
#define TC_WAIT_LD() asm volatile("tcgen05.wait::ld.sync.aligned;" ::: "memory")
#define FENCE_ASYNC() asm volatile("fence.proxy.async.shared::cta;" ::: "memory")

#define TC_LD_X32(r, a)                                                         \
    asm volatile("tcgen05.ld.sync.aligned.32x32b.x32.b32 "                      \
        "{%0, %1, %2, %3, %4, %5, %6, %7, %8, %9, %10, %11, %12, %13, %14, %15, " \
        " %16, %17, %18, %19, %20, %21, %22, %23, %24, %25, %26, %27, %28, %29, %30, %31}, [%32];" \
        : "=r"((r)[0]), "=r"((r)[1]), "=r"((r)[2]), "=r"((r)[3]),               \
          "=r"((r)[4]), "=r"((r)[5]), "=r"((r)[6]), "=r"((r)[7]),               \
          "=r"((r)[8]), "=r"((r)[9]), "=r"((r)[10]), "=r"((r)[11]),             \
          "=r"((r)[12]), "=r"((r)[13]), "=r"((r)[14]), "=r"((r)[15]),           \
          "=r"((r)[16]), "=r"((r)[17]), "=r"((r)[18]), "=r"((r)[19]),           \
          "=r"((r)[20]), "=r"((r)[21]), "=r"((r)[22]), "=r"((r)[23]),           \
          "=r"((r)[24]), "=r"((r)[25]), "=r"((r)[26]), "=r"((r)[27]),           \
          "=r"((r)[28]), "=r"((r)[29]), "=r"((r)[30]), "=r"((r)[31])            \
        : "r"(a))

// SW128 K-major smem descriptor: layout=2, version=1, SBO=64, LBO=1
#define DESC_BASE ((2ull << 61) | (1ull << 46) | (64ull << 32) | (1ull << 16))
#define MKDESC(addr) (DESC_BASE | ((uint64_t)((addr) >> 4) & 0x3FFF))

// idesc for kind::f16 (bf16 in, f32 acc): dtype F32@bit4, atype BF16@bit7,
// btype BF16@bit10, (N/8)@[17:23), (M/16)@[24:29)  (validated vs 0x8080490)
#define IDESC_BF16_N128 ((1u << 4) | (1u << 7) | (1u << 10) | (16u << 17) | (8u << 24))

__device__ __forceinline__ void tc_mma_bf16(uint32_t d, uint64_t ad, uint64_t bd,
                                            uint32_t idesc, uint32_t en) {
    asm volatile(
        "{\n\t.reg .pred p;\n\tsetp.ne.u32 p, %4, 0;\n\t"
        "tcgen05.mma.cta_group::1.kind::f16 [%0], %1, %2, %3, {%5, %5, %5, %5}, p;\n\t}"
        :: "r"(d), "l"(ad), "l"(bd), "r"(idesc), "r"(en), "r"(0u) : "memory");
}
#endif  // HAS_TC

// ---------------- preprocessing ----------------
__global__ void k_init() {
    if (threadIdx.x < 3) g_max[threadIdx.x] = 0u;
}

__global__ void k_maxabs_all(const float* __restrict__ x,
                             const float* __restrict__ w1f, const float* __restrict__ b1f,
                             const float* __restrict__ w2f, const float* __restrict__ b2f) {
    int which = blockIdx.y;
    const float* a;
    int na4, nb = 0;
    const float* b = nullptr;
    if (which == 0) { a = x; na4 = (M1 * K1) / 4; }
    else if (which == 1) { a = w1f; na4 = (K1 * N1) / 4; b = b1f; nb = N1; }
    else { a = w2f; na4 = (K2 * N2) / 4; b = b2f; nb = N2; }
    float m = 0.f;
    int tid = blockIdx.x * blockDim.x + threadIdx.x;
    int stride = gridDim.x * blockDim.x;
    const float4* a4 = (const float4*)a;
    for (int i = tid; i < na4; i += stride) {
        float4 v = a4[i];
        m = fmaxf(m, fmaxf(fmaxf(fabsf(v.x), fabsf(v.y)), fmaxf(fabsf(v.z), fabsf(v.w))));
    }
    for (int i = tid; i < nb; i += stride) m = fmaxf(m, fabsf(b[i]));
#pragma unroll
    for (int o = 16; o; o >>= 1) m = fmaxf(m, __shfl_xor_sync(0xFFFFFFFFu, m, o));
    if ((threadIdx.x & 31) == 0) atomicMax(&g_max[which], __float_as_uint(m));
}

__global__ void k_scales() {
    float mx = __uint_as_float(g_max[0]);
    float m1 = __uint_as_float(g_max[1]);
    float m2 = __uint_as_float(g_max[2]);
    float x_scale = __fdiv_rn(mx, 127.0f);
    float s1 = __fdiv_rn(m1, 127.0f);
    float s2 = __fdiv_rn(m2, 127.0f);
    g_scales[0] = x_scale;
    g_scales[1] = s1;
    g_scales[2] = s2;
    g_scales[3] = __fdiv_rn(__fmul_rn(x_scale, s1), s1);  // mult1
    g_scales[4] = __fdiv_rn(__fmul_rn(s1, s2), s2);       // mult2
}

// x: 4096 blocks cover all M1*K1/4 = 1048576 float4 groups; bias: 16 blocks
__global__ void k_quant_x_bias(const float* __restrict__ x,
                               const float* __restrict__ b1, const float* __restrict__ b2) {
    int bid = blockIdx.x;
    if (bid < 4096) {
        int i = bid * 256 + threadIdx.x;  // < M1*K1/4 = 1048576
        float s = g_scales[0];
        float4 v = ((const float4*)x)[i];
        float q0 = rintf(__fdiv_rn(v.x, s));
        float q1 = rintf(__fdiv_rn(v.y, s));
        float q2 = rintf(__fdiv_rn(v.z, s));
        float q3 = rintf(__fdiv_rn(v.w, s));
        uint2 o;
        o.x = pack_bf16(q0, q1);
        o.y = pack_bf16(q2, q3);
        ((uint2*)g_x16)[i] = o;
    } else {
        int j = (bid - 4096) * 256 + threadIdx.x;
        if (j < N1) g_b1q[j] = (short)(signed char)(int)rintf(__fdiv_rn(b1[j], g_scales[1]));
        if (j < N2) g_b2q[j] = (short)(signed char)(int)rintf(__fdiv_rn(b2[j], g_scales[2]));
    }
}

// w: [K][N] f32 row-major  ->  out: [N][K] bf16 (transposed, integer-exact)
__global__ void k_quant_w_all(const float* __restrict__ w1f, const float* __restrict__ w2f) {
    __shared__ float t[32][33];
    int id = blockIdx.x;
    const float* w;
    __nv_bfloat16* out;
    float s;
    int K, N, n0, k0;
    if (id < 4096) {
        w = w1f; out = g_w1t; s = g_scales[1]; K = K1; N = N1;
        n0 = (id & 127) * 32; k0 = (id >> 7) * 32;
    } else {
        int id2 = id - 4096;
        w = w2f; out = g_w2t; s = g_scales[2]; K = K2; N = N2;
        n0 = (id2 & 31) * 32; k0 = (id2 >> 5) * 32;
    }
    int tx = threadIdx.x & 31, ty = threadIdx.x >> 5;
#pragma unroll
    for (int j = 0; j < 32; j += 8)
        t[ty + j][tx] = w[(size_t)(k0 + ty + j) * N + (n0 + tx)];
    __syncthreads();
#pragma unroll
    for (int j = 0; j < 32; j += 8) {
        float v = rintf(__fdiv_rn(t[tx][ty + j], s));
        out[(size_t)(n0 + ty + j) * K + (k0 + tx)] = __float2bfloat16_rn(v);
    }
}

// smem layouts
#define G1_NS 4
#define G1_STAGE 32768               /* A 16KB + B 16KB (128 rows x 128B SW128) */
#define G1_SMEM (2048 + G1_NS * G1_STAGE)
#define G2_NS 3
#define G2_STAGE 65536               /* P0,P1,P2,B each 16KB */
#define G2_SMEM (2048 + G2_NS * G2_STAGE)

// ---------------- GEMM1: x16[4096,1024] @ w1t[4096,1024]^T (bf16 exact) ----------------
// grid (32,32), 256 thr, CTA 128x128, K-chunk 64 elems (128B)
__global__ void __launch_bounds__(256) k_gemm1() {
#if HAS_TC
    extern __shared__ __align__(16) unsigned char dyn1[];
    __shared__ short sb1[128];
    const uint32_t raw = smem_u32(dyn1);
    const uint32_t tb = (raw + 128 + 1023) & ~1023u;
    const int tid = threadIdx.x;
    const int wid = tid >> 5;
    const int bm = blockIdx.y * 128;
    const int bn = blockIdx.x * 128;

    if (tid < G1_NS) MBAR_INIT(raw + 8 * tid, 1);
    if (wid == 0) TC_ALLOC(raw + 64, 128);
    __syncthreads();
    uint32_t tmem;
    asm volatile("ld.shared.b32 %0, [%1];" : "=r"(tmem) : "r"(raw + 64));

    // loader mapping: 128 rows x 128B; each thread does 4x16B in one half-row
    const int row = tid >> 1;
    const int colb = (tid & 1) * 64;
    uint32_t swo[4];
#pragma unroll
    for (int j = 0; j < 4; j++) swo[j] = SW128(row * 128 + colb + j * 16);
    const char* Ag = (const char*)(g_x16 + (size_t)(bm + row) * K1) + colb;
    const char* Bg = (const char*)(g_w1t + (size_t)(bn + row) * K1) + colb;

    const int NK = K1 / 64;  // 16 chunks of 64 bf16 (128B)

#pragma unroll 1
    for (int di = 0; di < 2; di++) {
        uint32_t sa = tb + di * G1_STAGE;
#pragma unroll
        for (int j = 0; j < 4; j++) {
            cp16(sa + swo[j], Ag + di * 128 + j * 16);
            cp16(sa + 16384 + swo[j], Bg + di * 128 + j * 16);
        }
        cp_commit();
    }

#pragma unroll 1
    for (int i = 0; i < NK; i++) {
        int pf = i + 2;
        if (pf < NK) {
            if (i >= 2) MBAR_WAIT(raw + 8 * (pf % G1_NS), ((i - 2) / G1_NS) & 1);
            uint32_t sa = tb + (pf % G1_NS) * G1_STAGE;
#pragma unroll
            for (int j = 0; j < 4; j++) {
                cp16(sa + swo[j], Ag + pf * 128 + j * 16);
                cp16(sa + 16384 + swo[j], Bg + pf * 128 + j * 16);
            }
        }
        cp_commit();
        cp_wait<2>();
        __syncthreads();
        if (tid == 0) {
            FENCE_ASYNC();
            uint32_t sa = tb + (i % G1_NS) * G1_STAGE;
            uint64_t ad = MKDESC(sa), bd = MKDESC(sa + 16384);
#pragma unroll
            for (int k = 0; k < 4; k++)   // 4 x K=16 bf16 steps, +32B each
                tc_mma_bf16(tmem, ad + 2 * k, bd + 2 * k, IDESC_BF16_N128, (i | k) ? 1u : 0u);
            TC_COMMIT(raw + 8 * (i % G1_NS));
        }
    }

    if (tid < 128) sb1[tid] = g_b1q[bn + tid];
    __syncthreads();
    // final drain: stage (NK-1)%4 = 3 saw per-thread waits p0,p1,p0 (>=3 arrivals);
    // parity-1 wait now requires the 4th (last) arrival -> all MMAs complete
    MBAR_WAIT(raw + 8 * ((NK - 1) % G1_NS), 1);
    TC_FENCE_AFTER();

    if (tid < 128) {
        const float mult1 = g_scales[3];
        const int r = bm + tid;
#pragma unroll 1
        for (int cc = 0; cc < 4; cc++) {
            uint32_t d[32];
            TC_LD_X32(d, tmem + cc * 32);
            TC_WAIT_LD();
            unsigned w0[16], w1[16], w2[16];
#pragma unroll
            for (int g = 0; g < 16; g++) {
                float f0 = __uint_as_float(d[2 * g]);
                float f1 = __uint_as_float(d[2 * g + 1]);
                int q0 = (int)rintf(__fmul_rn(f0, mult1));
                int q1 = (int)rintf(__fmul_rn(f1, mult1));
                short o0 = (short)((short)q0 + sb1[cc * 32 + 2 * g]);
                short o1 = (short)((short)q1 + sb1[cc * 32 + 2 * g + 1]);
                if (o0 < 0) o0 = 0;
                if (o1 < 0) o1 = 0;
                w0[g] = pack_bf16((float)(o0 & 31), (float)(o1 & 31));
                w1[g] = pack_bf16((float)((o0 >> 5) & 31), (float)((o1 >> 5) & 31));
                w2[g] = pack_bf16((float)(o0 >> 10), (float)(o1 >> 10));
            }
            size_t ob = (size_t)r * N1 + bn + cc * 32;  // bf16 element index
#pragma unroll
            for (int q = 0; q < 4; q++) {
                ((uint4*)(g_p0 + ob))[q] = make_uint4(w0[4 * q], w0[4 * q + 1], w0[4 * q + 2], w0[4 * q + 3]);
                ((uint4*)(g_p1 + ob))[q] = make_uint4(w1[4 * q], w1[4 * q + 1], w1[4 * q + 2], w1[4 * q + 3]);
                ((uint4*)(g_p2 + ob))[q] = make_uint4(w2[4 * q], w2[4 * q + 1], w2[4 * q + 2], w2[4 * q + 3]);
            }
        }
        TC_FENCE_BEFORE();
    }
    __syncthreads();
    if (wid == 0) { TC_RELINQ(); TC_DEALLOC(tmem, 128); }
#else
    // fallback (compile-only on plain compute_103): naive but exact
    const int bm = blockIdx.y * 128;
    const int bn = blockIdx.x * 128;
    const float mult1 = g_scales[3];
    for (int o = threadIdx.x; o < 128 * 128; o += 256) {
        int r = bm + o / 128, c = bn + o % 128;
        float acc = 0.f;
        for (int k = 0; k < K1; k++)
            acc += __bfloat162float(g_x16[(size_t)r * K1 + k]) *
                   __bfloat162float(g_w1t[(size_t)c * K1 + k]);
        int q = (int)rintf(__fmul_rn(acc, mult1));
        short ov = (short)((short)q + g_b1q[c]);
        if (ov < 0) ov = 0;
        size_t idx = (size_t)r * N1 + c;
        g_p0[idx] = __float2bfloat16_rn((float)(ov & 31));
        g_p1[idx] = __float2bfloat16_rn((float)((ov >> 5) & 31));
        g_p2[idx] = __float2bfloat16_rn((float)(ov >> 10));
    }
#endif
}

// ---------------- GEMM2: 3-chain digit GEMM (bf16 exact) ----------------
// grid (8,32), 256 thr, CTA 128x128, K2=4096, K-chunk 64 elems
__global__ void __launch_bounds__(256) k_gemm2(float* __restrict__ out) {
#if HAS_TC
    extern __shared__ __align__(16) unsigned char dyn2[];
    __shared__ short sb2[128];
    const uint32_t raw = smem_u32(dyn2);
    const uint32_t tb = (raw + 128 + 1023) & ~1023u;
    const int tid = threadIdx.x;
    const int wid = tid >> 5;
    const int bm = blockIdx.y * 128;
    const int bn = blockIdx.x * 128;

    if (tid < G2_NS) MBAR_INIT(raw + 8 * tid, 1);
    if (wid == 0) TC_ALLOC(raw + 64, 512);
    __syncthreads();
    uint32_t tmem;
    asm volatile("ld.shared.b32 %0, [%1];" : "=r"(tmem) : "r"(raw + 64));
    const uint32_t D0 = tmem, D1 = tmem + 128, D2 = tmem + 256;

    const int row = tid >> 1;
    const int colb = (tid & 1) * 64;
    uint32_t swo[4];
#pragma unroll
    for (int j = 0; j < 4; j++) swo[j] = SW128(row * 128 + colb + j * 16);
    const char* P0g = (const char*)(g_p0 + (size_t)(bm + row) * K2) + colb;
    const char* P1g = (const char*)(g_p1 + (size_t)(bm + row) * K2) + colb;
    const char* P2g = (const char*)(g_p2 + (size_t)(bm + row) * K2) + colb;
    const char* Bg = (const char*)(g_w2t + (size_t)(bn + row) * K2) + colb;

    const int NK = K2 / 64;  // 64 chunks

#pragma unroll 1
    for (int di = 0; di < 2; di++) {
        uint32_t sa = tb + di * G2_STAGE;
#pragma unroll
        for (int j = 0; j < 4; j++) {
            cp16(sa + swo[j], P0g + di * 128 + j * 16);
            cp16(sa + 16384 + swo[j], P1g + di * 128 + j * 16);
            cp16(sa + 32768 + swo[j], P2g + di * 128 + j * 16);
            cp16(sa + 49152 + swo[j], Bg + di * 128 + j * 16);
        }
        cp_commit();
    }

#pragma unroll 1
    for (int i = 0; i < NK; i++) {
        int pf = i + 2;
        if (pf < NK) {
            if (i >= 1) MBAR_WAIT(raw + 8 * (pf % G2_NS), ((i - 1) / G2_NS) & 1);
            uint32_t sa = tb + (pf % G2_NS) * G2_STAGE;
#pragma unroll
            for (int j = 0; j < 4; j++) {
                cp16(sa + swo[j], P0g + pf * 128 + j * 16);
                cp16(sa + 16384 + swo[j], P1g + pf * 128 + j * 16);
                cp16(sa + 32768 + swo[j], P2g + pf * 128 + j * 16);
                cp16(sa + 49152 + swo[j], Bg + pf * 128 + j * 16);
            }
        }
        cp_commit();
        cp_wait<2>();
        __syncthreads();
        if (tid == 0) {
            FENCE_ASYNC();
            uint32_t sa = tb + (i % G2_NS) * G2_STAGE;
            uint64_t p0d = MKDESC(sa), p1d = MKDESC(sa + 16384);
            uint64_t p2d = MKDESC(sa + 32768), bd = MKDESC(sa + 49152);
#pragma unroll
            for (int k = 0; k < 4; k++) {
                uint32_t en = (i | k) ? 1u : 0u;
                tc_mma_bf16(D0, p0d + 2 * k, bd + 2 * k, IDESC_BF16_N128, en);
                tc_mma_bf16(D1, p1d + 2 * k, bd + 2 * k, IDESC_BF16_N128, en);
                tc_mma_bf16(D2, p2d + 2 * k, bd + 2 * k, IDESC_BF16_N128, en);
            }
            TC_COMMIT(raw + 8 * (i % G2_NS));
        }
    }

    if (tid < 128) sb2[tid] = g_b2q[bn + tid];
    __syncthreads();
    // final drain: stage (NK-1)%3 = 0 saw per-thread producer waits up to arrival 21;
    // parity-1 wait now requires arrival 22 (the last commit) -> all MMAs complete
    MBAR_WAIT(raw + 8 * ((NK - 1) % G2_NS), 1);
    TC_FENCE_AFTER();

    if (tid < 128) {
        const float mult2 = g_scales[4];
        const float s2 = g_scales[2];
        const int r = bm + tid;
#pragma unroll 1
        for (int cc = 0; cc < 4; cc++) {
            uint32_t d0[32], d1[32], d2[32];
            TC_LD_X32(d0, D0 + cc * 32);
            TC_LD_X32(d1, D1 + cc * 32);
            TC_LD_X32(d2, D2 + cc * 32);
            TC_WAIT_LD();
            float res[32];
#pragma unroll
            for (int e = 0; e < 32; e++) {
                int a0 = (int)__uint_as_float(d0[e]);
                int a1 = (int)__uint_as_float(d1[e]);
                int a2 = (int)__uint_as_float(d2[e]);
                int v = (int)(((unsigned)a2 << 10) + ((unsigned)a1 << 5) + (unsigned)a0);
                int q = (int)rintf(__fmul_rn((float)v, mult2));
                short o = (short)((short)q + sb2[cc * 32 + e]);
                res[e] = __fmul_rn((float)o, s2);
            }
            float* ob = out + (size_t)r * N2 + bn + cc * 32;
#pragma unroll
            for (int g = 0; g < 8; g++)
                ((float4*)ob)[g] = make_float4(res[4 * g], res[4 * g + 1],
                                               res[4 * g + 2], res[4 * g + 3]);
        }
        TC_FENCE_BEFORE();
    }
    __syncthreads();
    if (wid == 0) { TC_RELINQ(); TC_DEALLOC(tmem, 512); }
#else
    // fallback (compile-only): naive but exact 3-chain accumulate
    const int bm = blockIdx.y * 128;
    const int bn = blockIdx.x * 128;
    const float mult2 = g_scales[4];
    const float s2 = g_scales[2];
    for (int o = threadIdx.x; o < 128 * 128; o += 256) {
        int r = bm + o / 128, c = bn + o % 128;
        float a0 = 0.f, a1 = 0.f, a2 = 0.f;
        for (int k = 0; k < K2; k++) {
            float w = __bfloat162float(g_w2t[(size_t)c * K2 + k]);
            a0 += __bfloat162float(g_p0[(size_t)r * K2 + k]) * w;
            a1 += __bfloat162float(g_p1[(size_t)r * K2 + k]) * w;
            a2 += __bfloat162float(g_p2[(size_t)r * K2 + k]) * w;
        }
        int v = (int)(((unsigned)(int)a2 << 10) + ((unsigned)(int)a1 << 5) + (unsigned)(int)a0);
        int q = (int)rintf(__fmul_rn((float)v, mult2));
        short ov = (short)((short)q + g_b2q[c]);
        out[(size_t)r * N2 + c] = __fmul_rn((float)ov, s2);
    }
#endif
}

// ---------------- launcher ----------------
extern "C" void kernel_launch(void* const* d_in, const int* in_sizes, int n_in,
                              void* d_out, int out_size) {
    const float* x = (const float*)d_in[0];    // [4096, 1024]
    const float* w1f = (const float*)d_in[1];  // [1024, 4096]
    const float* b1f = (const float*)d_in[2];  // [4096]
    const float* w2f = (const float*)d_in[3];  // [4096, 1024]
    const float* b2f = (const float*)d_in[4];  // [1024]
    float* out = (float*)d_out;                // [4096, 1024]

    static bool attr_done = false;
    if (!attr_done) {
        cudaFuncSetAttribute(k_gemm1, cudaFuncAttributeMaxDynamicSharedMemorySize, G1_SMEM);
        cudaFuncSetAttribute(k_gemm2, cudaFuncAttributeMaxDynamicSharedMemorySize, G2_SMEM);
        attr_done = true;
    }

    k_init<<<1, 32>>>();                                           // launch 0
    k_maxabs_all<<<dim3(1024, 3), 256>>>(x, w1f, b1f, w2f, b2f);   // launch 1
    k_scales<<<1, 1>>>();                                          // launch 2
    k_quant_x_bias<<<4112, 256>>>(x, b1f, b2f);                    // launch 3 (FIX: full x)
    k_quant_w_all<<<8192, 256>>>(w1f, w2f);                        // launch 4
    k_gemm1<<<dim3(N1 / 128, M1 / 128), 256, G1_SMEM>>>();         // launch 5 (ncu slot)
    k_gemm2<<<dim3(N2 / 128, M1 / 128), 256, G2_SMEM>>>(out);      // launch 6
}